// round 1
// baseline (speedup 1.0000x reference)
#include <cuda_runtime.h>
#include <cuda_bf16.h>

#define S_LEN 2048
#define DM    1024
#define NH    16
#define DKH   64
#define BB    2

// scratch: [B,H,S,DK] layouts
__device__ float g_q[BB*NH*S_LEN*DKH];
__device__ float g_k[BB*NH*S_LEN*DKH];
__device__ float g_v[BB*NH*S_LEN*DKH];
__device__ float g_attn[BB*NH*S_LEN*DKH];

// ---------------------------------------------------------------------------
// QKV projection: out[b,h,s,dk] = X[b,s,:] @ W[n,:]^T + bias[n], n = h*64+dk
// 64x64 block tile, BK=16, 256 threads, 4x4 per thread. grid.z selects Q/K/V.
// ---------------------------------------------------------------------------
__global__ __launch_bounds__(256) void qkv_proj_kernel(
    const float* __restrict__ xq, const float* __restrict__ xk, const float* __restrict__ xv,
    const float* __restrict__ Wq, const float* __restrict__ bq,
    const float* __restrict__ Wk, const float* __restrict__ bk,
    const float* __restrict__ Wv, const float* __restrict__ bv)
{
    int z = blockIdx.z;
    const float* X    = (z == 0) ? xq : (z == 1) ? xk : xv;
    const float* W    = (z == 0) ? Wq : (z == 1) ? Wk : Wv;
    const float* bias = (z == 0) ? bq : (z == 1) ? bk : bv;
    float* out        = (z == 0) ? g_q : (z == 1) ? g_k : g_v;

    __shared__ float As[16][64];   // [k][m]
    __shared__ float Bs[16][64];   // [k][n]

    int tid = threadIdx.x;
    int m0 = blockIdx.y * 64;
    int n0 = blockIdx.x * 64;
    int tx = tid & 15, ty = tid >> 4;
    int lrow = tid >> 2;          // 0..63
    int lcol = (tid & 3) * 4;     // 0,4,8,12

    float acc[4][4] = {};

    for (int k0 = 0; k0 < DM; k0 += 16) {
        float4 a = *(const float4*)&X[(size_t)(m0 + lrow) * DM + k0 + lcol];
        float4 b = *(const float4*)&W[(size_t)(n0 + lrow) * DM + k0 + lcol];
        __syncthreads();
        As[lcol + 0][lrow] = a.x; As[lcol + 1][lrow] = a.y;
        As[lcol + 2][lrow] = a.z; As[lcol + 3][lrow] = a.w;
        Bs[lcol + 0][lrow] = b.x; Bs[lcol + 1][lrow] = b.y;
        Bs[lcol + 2][lrow] = b.z; Bs[lcol + 3][lrow] = b.w;
        __syncthreads();
        #pragma unroll
        for (int kk = 0; kk < 16; kk++) {
            float av[4], bv4[4];
            #pragma unroll
            for (int i = 0; i < 4; i++) av[i]  = As[kk][ty * 4 + i];
            #pragma unroll
            for (int j = 0; j < 4; j++) bv4[j] = Bs[kk][tx * 4 + j];
            #pragma unroll
            for (int i = 0; i < 4; i++)
                #pragma unroll
                for (int j = 0; j < 4; j++)
                    acc[i][j] += av[i] * bv4[j];
        }
    }

    #pragma unroll
    for (int i = 0; i < 4; i++) {
        int m = m0 + ty * 4 + i;
        int b_ = m >> 11, s = m & 2047;
        #pragma unroll
        for (int j = 0; j < 4; j++) {
            int n = n0 + tx * 4 + j;
            int h = n >> 6, dk = n & 63;
            out[(((size_t)(b_ * NH + h)) * S_LEN + s) * DKH + dk] = acc[i][j] + bias[n];
        }
    }
}

// ---------------------------------------------------------------------------
// Flash attention: block = (q-tile of 64 rows, one (b,h)). kv tiles of 64.
// Thread (rg,cg) owns rows 4rg..4rg+3 and cols 4cg..4cg+3.
// Smem: Qt [d][r], KP [d][k] (reused as Pt [k][r]), Vs [k][d]. 48KB exactly.
// ---------------------------------------------------------------------------
__global__ __launch_bounds__(256) void attn_kernel(const int* __restrict__ mask)
{
    __shared__ float Qt[64][64];   // transposed Q: [d][r]
    __shared__ float KP[64][64];   // Kt: [d][k], reused as Pt: [k][r]
    __shared__ float Vs[64][64];   // [k][d]

    int tid = threadIdx.x;
    int bh = blockIdx.y;
    int b  = bh >> 4;
    int q0 = blockIdx.x * 64;
    int rg = tid >> 4;     // 0..15
    int cg = tid & 15;     // 0..15

    const float* Qg = g_q + (size_t)bh * S_LEN * DKH;
    const float* Kg = g_k + (size_t)bh * S_LEN * DKH;
    const float* Vg = g_v + (size_t)bh * S_LEN * DKH;

    // load Q tile transposed
    {
        int row = tid >> 2;
        int col = (tid & 3) * 16;
        #pragma unroll
        for (int c = 0; c < 16; c += 4) {
            float4 v = *(const float4*)&Qg[(size_t)(q0 + row) * DKH + col + c];
            Qt[col + c + 0][row] = v.x; Qt[col + c + 1][row] = v.y;
            Qt[col + c + 2][row] = v.z; Qt[col + c + 3][row] = v.w;
        }
    }

    float m_i[4] = {-1e30f, -1e30f, -1e30f, -1e30f};
    float l_i[4] = {0.f, 0.f, 0.f, 0.f};
    float o[4][4] = {};

    for (int k0 = 0; k0 < S_LEN; k0 += 64) {
        __syncthreads();   // prior iteration's PV reads of KP/Vs done
        {
            int row = tid >> 2;
            int col = (tid & 3) * 16;
            #pragma unroll
            for (int c = 0; c < 16; c += 4) {
                float4 kv = *(const float4*)&Kg[(size_t)(k0 + row) * DKH + col + c];
                KP[col + c + 0][row] = kv.x; KP[col + c + 1][row] = kv.y;
                KP[col + c + 2][row] = kv.z; KP[col + c + 3][row] = kv.w;
                float4 vv = *(const float4*)&Vg[(size_t)(k0 + row) * DKH + col + c];
                *(float4*)&Vs[row][col + c] = vv;
            }
        }
        __syncthreads();

        // S = Q K^T (4x4 per thread)
        float s[4][4] = {};
        #pragma unroll 16
        for (int d = 0; d < 64; d++) {
            float4 a  = *(const float4*)&Qt[d][rg * 4];
            float4 b4 = *(const float4*)&KP[d][cg * 4];
            float av[4] = {a.x, a.y, a.z, a.w};
            float bv[4] = {b4.x, b4.y, b4.z, b4.w};
            #pragma unroll
            for (int i = 0; i < 4; i++)
                #pragma unroll
                for (int j = 0; j < 4; j++)
                    s[i][j] += av[i] * bv[j];
        }

        // scale + mask (scores/8; masked -> -1e9, exactly as reference)
        #pragma unroll
        for (int i = 0; i < 4; i++) {
            int4 mv = *(const int4*)&mask[((size_t)b * S_LEN + q0 + rg * 4 + i) * S_LEN
                                          + k0 + cg * 4];
            s[i][0] = mv.x ? s[i][0] * 0.125f : -1e9f;
            s[i][1] = mv.y ? s[i][1] * 0.125f : -1e9f;
            s[i][2] = mv.z ? s[i][2] * 0.125f : -1e9f;
            s[i][3] = mv.w ? s[i][3] * 0.125f : -1e9f;
        }

        // online softmax per row; row group = 16 consecutive lanes
        #pragma unroll
        for (int i = 0; i < 4; i++) {
            float mx = fmaxf(fmaxf(s[i][0], s[i][1]), fmaxf(s[i][2], s[i][3]));
            #pragma unroll
            for (int off = 1; off < 16; off <<= 1)
                mx = fmaxf(mx, __shfl_xor_sync(0xffffffffu, mx, off));
            float mnew  = fmaxf(m_i[i], mx);
            float alpha = __expf(m_i[i] - mnew);
            m_i[i] = mnew;
            float ls = 0.f;
            #pragma unroll
            for (int j = 0; j < 4; j++) { s[i][j] = __expf(s[i][j] - mnew); ls += s[i][j]; }
            #pragma unroll
            for (int off = 1; off < 16; off <<= 1)
                ls += __shfl_xor_sync(0xffffffffu, ls, off);
            l_i[i] = l_i[i] * alpha + ls;
            #pragma unroll
            for (int j = 0; j < 4; j++) o[i][j] *= alpha;
        }

        __syncthreads();   // everyone done reading Kt before reuse as Pt
        #pragma unroll
        for (int i = 0; i < 4; i++)
            #pragma unroll
            for (int j = 0; j < 4; j++)
                KP[cg * 4 + j][rg * 4 + i] = s[i][j];   // Pt[k][r]
        __syncwarp();      // P row exchange is intra-warp (16-lane row groups)

        // O += P @ V
        #pragma unroll 16
        for (int k = 0; k < 64; k++) {
            float4 p  = *(const float4*)&KP[k][rg * 4];
            float4 v4 = *(const float4*)&Vs[k][cg * 4];
            float pv[4] = {p.x, p.y, p.z, p.w};
            float vv[4] = {v4.x, v4.y, v4.z, v4.w};
            #pragma unroll
            for (int i = 0; i < 4; i++)
                #pragma unroll
                for (int j = 0; j < 4; j++)
                    o[i][j] += pv[i] * vv[j];
        }
    }

    #pragma unroll
    for (int i = 0; i < 4; i++) {
        float inv = 1.0f / l_i[i];
        float4 r4 = make_float4(o[i][0] * inv, o[i][1] * inv, o[i][2] * inv, o[i][3] * inv);
        *(float4*)&g_attn[((size_t)bh * S_LEN + q0 + rg * 4 + i) * DKH + cg * 4] = r4;
    }
}

// ---------------------------------------------------------------------------
// Output projection: out[b,s,n] = attn[b,s,:] (head-gathered) @ Wo[n,:]^T + bo
// ---------------------------------------------------------------------------
__global__ __launch_bounds__(256) void out_proj_kernel(
    const float* __restrict__ Wo, const float* __restrict__ bo, float* __restrict__ out)
{
    __shared__ float As[16][64];
    __shared__ float Bs[16][64];

    int tid = threadIdx.x;
    int m0 = blockIdx.y * 64;
    int n0 = blockIdx.x * 64;
    int tx = tid & 15, ty = tid >> 4;
    int lrow = tid >> 2;
    int lcol = (tid & 3) * 4;

    int m  = m0 + lrow;
    int b_ = m >> 11, ss = m & 2047;

    float acc[4][4] = {};

    for (int k0 = 0; k0 < DM; k0 += 16) {
        int kk0 = k0 + lcol;
        int h = kk0 >> 6, dk = kk0 & 63;   // BK=16 tile never crosses a head boundary
        float4 a = *(const float4*)&g_attn[(((size_t)(b_ * NH + h)) * S_LEN + ss) * DKH + dk];
        float4 b = *(const float4*)&Wo[(size_t)(n0 + lrow) * DM + kk0];
        __syncthreads();
        As[lcol + 0][lrow] = a.x; As[lcol + 1][lrow] = a.y;
        As[lcol + 2][lrow] = a.z; As[lcol + 3][lrow] = a.w;
        Bs[lcol + 0][lrow] = b.x; Bs[lcol + 1][lrow] = b.y;
        Bs[lcol + 2][lrow] = b.z; Bs[lcol + 3][lrow] = b.w;
        __syncthreads();
        #pragma unroll
        for (int kk = 0; kk < 16; kk++) {
            float av[4], bv4[4];
            #pragma unroll
            for (int i = 0; i < 4; i++) av[i]  = As[kk][ty * 4 + i];
            #pragma unroll
            for (int j = 0; j < 4; j++) bv4[j] = Bs[kk][tx * 4 + j];
            #pragma unroll
            for (int i = 0; i < 4; i++)
                #pragma unroll
                for (int j = 0; j < 4; j++)
                    acc[i][j] += av[i] * bv4[j];
        }
    }

    #pragma unroll
    for (int i = 0; i < 4; i++) {
        size_t mrow = (size_t)(m0 + ty * 4 + i) * DM;
        #pragma unroll
        for (int j = 0; j < 4; j++) {
            int n = n0 + tx * 4 + j;
            out[mrow + n] = acc[i][j] + bo[n];
        }
    }
}

extern "C" void kernel_launch(void* const* d_in, const int* in_sizes, int n_in,
                              void* d_out, int out_size)
{
    const float* query = (const float*)d_in[0];
    const float* key_  = (const float*)d_in[1];
    const float* value = (const float*)d_in[2];
    const int*   mask  = (const int*)d_in[3];
    const float* Wq = (const float*)d_in[4];
    const float* bq = (const float*)d_in[5];
    const float* Wk = (const float*)d_in[6];
    const float* bk = (const float*)d_in[7];
    const float* Wv = (const float*)d_in[8];
    const float* bv = (const float*)d_in[9];
    const float* Wo = (const float*)d_in[10];
    const float* bo = (const float*)d_in[11];
    float* out = (float*)d_out;

    dim3 g1(DM / 64, (BB * S_LEN) / 64, 3);
    qkv_proj_kernel<<<g1, 256>>>(query, key_, value, Wq, bq, Wk, bk, Wv, bv);

    dim3 g2(S_LEN / 64, BB * NH);
    attn_kernel<<<g2, 256>>>(mask);

    dim3 g3(DM / 64, (BB * S_LEN) / 64);
    out_proj_kernel<<<g3, 256>>>(Wo, bo, out);
}

// round 2
// speedup vs baseline: 1.2014x; 1.2014x over previous
#include <cuda_runtime.h>
#include <cuda_bf16.h>

#define S_LEN 2048
#define DM    1024
#define NH    16
#define DKH   64
#define BB    2

// scratch: [B,H,S,DK] layouts
__device__ float g_q[BB*NH*S_LEN*DKH];
__device__ float g_k[BB*NH*S_LEN*DKH];
__device__ float g_v[BB*NH*S_LEN*DKH];
__device__ float g_attn[BB*NH*S_LEN*DKH];

// ---------------------------------------------------------------------------
// QKV projection: out[b,h,s,dk] = X[b,s,:] @ W[n,:]^T + bias[n], n = h*64+dk
// 128x128 tile, BK=16, 256 threads, 8x8 micro-tile. grid.z selects Q/K/V.
// ---------------------------------------------------------------------------
__global__ __launch_bounds__(256) void qkv_proj_kernel(
    const float* __restrict__ xq, const float* __restrict__ xk, const float* __restrict__ xv,
    const float* __restrict__ Wq, const float* __restrict__ bq,
    const float* __restrict__ Wk, const float* __restrict__ bk,
    const float* __restrict__ Wv, const float* __restrict__ bv)
{
    int z = blockIdx.z;
    const float* X    = (z == 0) ? xq : (z == 1) ? xk : xv;
    const float* W    = (z == 0) ? Wq : (z == 1) ? Wk : Wv;
    const float* bias = (z == 0) ? bq : (z == 1) ? bk : bv;
    float* out        = (z == 0) ? g_q : (z == 1) ? g_k : g_v;

    __shared__ __align__(16) float As[16][132];   // [k][m], pad 132
    __shared__ __align__(16) float Bs[16][132];   // [k][n]

    int tid = threadIdx.x;
    int m0 = blockIdx.y * 128;
    int n0 = blockIdx.x * 128;
    int ty = tid >> 4, tx = tid & 15;
    int lrow = tid >> 1;           // 0..127
    int lc0  = (tid & 1) * 8;      // 0 or 8

    const float* Abase = X + (size_t)(m0 + lrow) * DM + lc0;
    const float* Bbase = W + (size_t)(n0 + lrow) * DM + lc0;

    float4 a0 = *(const float4*)(Abase + 0);
    float4 a1 = *(const float4*)(Abase + 4);
    float4 b0 = *(const float4*)(Bbase + 0);
    float4 b1 = *(const float4*)(Bbase + 4);

    float acc[8][8] = {};

    for (int k0 = 0; k0 < DM; k0 += 16) {
        __syncthreads();
        As[lc0 + 0][lrow] = a0.x; As[lc0 + 1][lrow] = a0.y;
        As[lc0 + 2][lrow] = a0.z; As[lc0 + 3][lrow] = a0.w;
        As[lc0 + 4][lrow] = a1.x; As[lc0 + 5][lrow] = a1.y;
        As[lc0 + 6][lrow] = a1.z; As[lc0 + 7][lrow] = a1.w;
        Bs[lc0 + 0][lrow] = b0.x; Bs[lc0 + 1][lrow] = b0.y;
        Bs[lc0 + 2][lrow] = b0.z; Bs[lc0 + 3][lrow] = b0.w;
        Bs[lc0 + 4][lrow] = b1.x; Bs[lc0 + 5][lrow] = b1.y;
        Bs[lc0 + 6][lrow] = b1.z; Bs[lc0 + 7][lrow] = b1.w;
        __syncthreads();
        if (k0 + 16 < DM) {
            a0 = *(const float4*)(Abase + k0 + 16);
            a1 = *(const float4*)(Abase + k0 + 20);
            b0 = *(const float4*)(Bbase + k0 + 16);
            b1 = *(const float4*)(Bbase + k0 + 20);
        }
        #pragma unroll
        for (int kk = 0; kk < 16; kk++) {
            float4 av0 = *(const float4*)&As[kk][ty * 8];
            float4 av1 = *(const float4*)&As[kk][ty * 8 + 4];
            float4 bv0 = *(const float4*)&Bs[kk][tx * 8];
            float4 bv1 = *(const float4*)&Bs[kk][tx * 8 + 4];
            float av[8] = {av0.x, av0.y, av0.z, av0.w, av1.x, av1.y, av1.z, av1.w};
            float bvv[8] = {bv0.x, bv0.y, bv0.z, bv0.w, bv1.x, bv1.y, bv1.z, bv1.w};
            #pragma unroll
            for (int i = 0; i < 8; i++)
                #pragma unroll
                for (int j = 0; j < 8; j++)
                    acc[i][j] += av[i] * bvv[j];
        }
    }

    // epilogue: bias + scatter to [B,H,S,DK]
    int nbase = n0 + tx * 8;           // 8 consecutive cols, within one head
    int h = nbase >> 6, dk = nbase & 63;
    float bj[8];
    #pragma unroll
    for (int j = 0; j < 8; j++) bj[j] = bias[nbase + j];

    #pragma unroll
    for (int i = 0; i < 8; i++) {
        int m = m0 + ty * 8 + i;
        int b_ = m >> 11, s = m & 2047;
        float* op = out + (((size_t)(b_ * NH + h)) * S_LEN + s) * DKH + dk;
        float4 r0 = make_float4(acc[i][0] + bj[0], acc[i][1] + bj[1],
                                acc[i][2] + bj[2], acc[i][3] + bj[3]);
        float4 r1 = make_float4(acc[i][4] + bj[4], acc[i][5] + bj[5],
                                acc[i][6] + bj[6], acc[i][7] + bj[7]);
        *(float4*)(op + 0) = r0;
        *(float4*)(op + 4) = r1;
    }
}

// ---------------------------------------------------------------------------
// Flash attention: block = (64 q rows, one (b,h)). kv tiles of 64.
// 128 threads: rg = tid>>4 (0..7) owns 8 rows, cg = tid&15 owns 4 cols.
// Smem: Qt [d][r] 16KB, KP (Kt [d][k], reused as P [r][k]) 16KB, Vs [k][d] 16KB.
// ---------------------------------------------------------------------------
__global__ __launch_bounds__(128) void attn_kernel(const int* __restrict__ mask)
{
    __shared__ __align__(16) float Qt[64][64];   // [d][r]
    __shared__ __align__(16) float KP[64][64];   // Kt: [d][k]; reused as P: [r][k]
    __shared__ __align__(16) float Vs[64][64];   // [k][d]

    int tid = threadIdx.x;
    int bh = blockIdx.y;
    int b  = bh >> 4;
    int q0 = blockIdx.x * 64;
    int rg = tid >> 4;     // 0..7
    int cg = tid & 15;     // 0..15

    const float* Qg = g_q + (size_t)bh * S_LEN * DKH;
    const float* Kg = g_k + (size_t)bh * S_LEN * DKH;
    const float* Vg = g_v + (size_t)bh * S_LEN * DKH;

    // load Q tile transposed: row = tid>>1 (0..63), c0 = (tid&1)*32
    {
        int row = tid >> 1;
        int c0 = (tid & 1) * 32;
        #pragma unroll
        for (int c = 0; c < 32; c += 4) {
            float4 v = *(const float4*)&Qg[(size_t)(q0 + row) * DKH + c0 + c];
            Qt[c0 + c + 0][row] = v.x; Qt[c0 + c + 1][row] = v.y;
            Qt[c0 + c + 2][row] = v.z; Qt[c0 + c + 3][row] = v.w;
        }
    }

    float m_i[8], l_i[8];
    #pragma unroll
    for (int i = 0; i < 8; i++) { m_i[i] = -1e30f; l_i[i] = 0.f; }
    float o[8][4] = {};

    for (int k0 = 0; k0 < S_LEN; k0 += 64) {
        __syncthreads();   // prior iteration's PV reads of KP/Vs done
        {
            int row = tid >> 1;
            int c0 = (tid & 1) * 32;
            #pragma unroll
            for (int c = 0; c < 32; c += 4) {
                float4 kv = *(const float4*)&Kg[(size_t)(k0 + row) * DKH + c0 + c];
                KP[c0 + c + 0][row] = kv.x; KP[c0 + c + 1][row] = kv.y;
                KP[c0 + c + 2][row] = kv.z; KP[c0 + c + 3][row] = kv.w;
                float4 vv = *(const float4*)&Vg[(size_t)(k0 + row) * DKH + c0 + c];
                *(float4*)&Vs[row][c0 + c] = vv;
            }
        }
        __syncthreads();

        // S = Q K^T (8x4 per thread)
        float s[8][4] = {};
        #pragma unroll 8
        for (int d = 0; d < 64; d++) {
            float4 av0 = *(const float4*)&Qt[d][rg * 8];
            float4 av1 = *(const float4*)&Qt[d][rg * 8 + 4];
            float4 b4  = *(const float4*)&KP[d][cg * 4];
            float av[8] = {av0.x, av0.y, av0.z, av0.w, av1.x, av1.y, av1.z, av1.w};
            float bv[4] = {b4.x, b4.y, b4.z, b4.w};
            #pragma unroll
            for (int i = 0; i < 8; i++)
                #pragma unroll
                for (int j = 0; j < 4; j++)
                    s[i][j] += av[i] * bv[j];
        }

        // scale + mask (scores/8; masked -> -1e9, exactly as reference)
        const int* mbase = mask + ((size_t)b * S_LEN + q0 + rg * 8) * S_LEN + k0 + cg * 4;
        #pragma unroll
        for (int i = 0; i < 8; i++) {
            int4 mv = *(const int4*)(mbase + (size_t)i * S_LEN);
            s[i][0] = mv.x ? s[i][0] * 0.125f : -1e9f;
            s[i][1] = mv.y ? s[i][1] * 0.125f : -1e9f;
            s[i][2] = mv.z ? s[i][2] * 0.125f : -1e9f;
            s[i][3] = mv.w ? s[i][3] * 0.125f : -1e9f;
        }

        // online softmax per row; row group = 16 consecutive lanes
        #pragma unroll
        for (int i = 0; i < 8; i++) {
            float mx = fmaxf(fmaxf(s[i][0], s[i][1]), fmaxf(s[i][2], s[i][3]));
            #pragma unroll
            for (int off = 1; off < 16; off <<= 1)
                mx = fmaxf(mx, __shfl_xor_sync(0xffffffffu, mx, off));
            float mnew  = fmaxf(m_i[i], mx);
            float alpha = __expf(m_i[i] - mnew);
            m_i[i] = mnew;
            float ls = 0.f;
            #pragma unroll
            for (int j = 0; j < 4; j++) { s[i][j] = __expf(s[i][j] - mnew); ls += s[i][j]; }
            #pragma unroll
            for (int off = 1; off < 16; off <<= 1)
                ls += __shfl_xor_sync(0xffffffffu, ls, off);
            l_i[i] = l_i[i] * alpha + ls;
            #pragma unroll
            for (int j = 0; j < 4; j++) o[i][j] *= alpha;
        }

        __syncthreads();   // everyone done reading Kt before reuse as P
        // store P in natural orientation [r][k], vectorized (conflict-free)
        #pragma unroll
        for (int i = 0; i < 8; i++)
            *(float4*)&KP[rg * 8 + i][cg * 4] = make_float4(s[i][0], s[i][1], s[i][2], s[i][3]);
        __syncwarp();      // P row exchange is intra-half-warp (16-lane row groups)

        // O += P @ V, reading P as float4 along k
        #pragma unroll 4
        for (int k4 = 0; k4 < 64; k4 += 4) {
            float4 v0 = *(const float4*)&Vs[k4 + 0][cg * 4];
            float4 v1 = *(const float4*)&Vs[k4 + 1][cg * 4];
            float4 v2 = *(const float4*)&Vs[k4 + 2][cg * 4];
            float4 v3 = *(const float4*)&Vs[k4 + 3][cg * 4];
            #pragma unroll
            for (int i = 0; i < 8; i++) {
                float4 p = *(const float4*)&KP[rg * 8 + i][k4];
                o[i][0] += p.x * v0.x + p.y * v1.x + p.z * v2.x + p.w * v3.x;
                o[i][1] += p.x * v0.y + p.y * v1.y + p.z * v2.y + p.w * v3.y;
                o[i][2] += p.x * v0.z + p.y * v1.z + p.z * v2.z + p.w * v3.z;
                o[i][3] += p.x * v0.w + p.y * v1.w + p.z * v2.w + p.w * v3.w;
            }
        }
    }

    #pragma unroll
    for (int i = 0; i < 8; i++) {
        float inv = 1.0f / l_i[i];
        float4 r4 = make_float4(o[i][0] * inv, o[i][1] * inv, o[i][2] * inv, o[i][3] * inv);
        *(float4*)&g_attn[((size_t)bh * S_LEN + q0 + rg * 8 + i) * DKH + cg * 4] = r4;
    }
}

// ---------------------------------------------------------------------------
// Output projection: out[b,s,n] = attn[b,s,:] (head-gathered) @ Wo[n,:]^T + bo
// 128x128 tile, BK=16, 256 threads, 8x8 micro-tile.
// ---------------------------------------------------------------------------
__global__ __launch_bounds__(256) void out_proj_kernel(
    const float* __restrict__ Wo, const float* __restrict__ bo, float* __restrict__ out)
{
    __shared__ __align__(16) float As[16][132];
    __shared__ __align__(16) float Bs[16][132];

    int tid = threadIdx.x;
    int m0 = blockIdx.y * 128;
    int n0 = blockIdx.x * 128;
    int ty = tid >> 4, tx = tid & 15;
    int lrow = tid >> 1;
    int lc0  = (tid & 1) * 8;

    int m  = m0 + lrow;
    int b_ = m >> 11, ss = m & 2047;
    const float* arow = g_attn + ((size_t)b_ * NH) * S_LEN * DKH + (size_t)ss * DKH;
    // element k of logical row: arow[(k>>6)*S_LEN*DKH + (k&63)]
    const float* Bbase = Wo + (size_t)(n0 + lrow) * DM + lc0;

    auto lda = [&](int k) -> float4 {
        return *(const float4*)(arow + (size_t)(k >> 6) * (S_LEN * DKH) + (k & 63));
    };

    float4 a0 = lda(lc0);
    float4 a1 = lda(lc0 + 4);
    float4 b0 = *(const float4*)(Bbase + 0);
    float4 b1 = *(const float4*)(Bbase + 4);

    float acc[8][8] = {};

    for (int k0 = 0; k0 < DM; k0 += 16) {
        __syncthreads();
        As[lc0 + 0][lrow] = a0.x; As[lc0 + 1][lrow] = a0.y;
        As[lc0 + 2][lrow] = a0.z; As[lc0 + 3][lrow] = a0.w;
        As[lc0 + 4][lrow] = a1.x; As[lc0 + 5][lrow] = a1.y;
        As[lc0 + 6][lrow] = a1.z; As[lc0 + 7][lrow] = a1.w;
        Bs[lc0 + 0][lrow] = b0.x; Bs[lc0 + 1][lrow] = b0.y;
        Bs[lc0 + 2][lrow] = b0.z; Bs[lc0 + 3][lrow] = b0.w;
        Bs[lc0 + 4][lrow] = b1.x; Bs[lc0 + 5][lrow] = b1.y;
        Bs[lc0 + 6][lrow] = b1.z; Bs[lc0 + 7][lrow] = b1.w;
        __syncthreads();
        if (k0 + 16 < DM) {
            a0 = lda(k0 + 16 + lc0);
            a1 = lda(k0 + 20 + lc0);
            b0 = *(const float4*)(Bbase + k0 + 16);
            b1 = *(const float4*)(Bbase + k0 + 20);
        }
        #pragma unroll
        for (int kk = 0; kk < 16; kk++) {
            float4 av0 = *(const float4*)&As[kk][ty * 8];
            float4 av1 = *(const float4*)&As[kk][ty * 8 + 4];
            float4 bv0 = *(const float4*)&Bs[kk][tx * 8];
            float4 bv1 = *(const float4*)&Bs[kk][tx * 8 + 4];
            float av[8] = {av0.x, av0.y, av0.z, av0.w, av1.x, av1.y, av1.z, av1.w};
            float bvv[8] = {bv0.x, bv0.y, bv0.z, bv0.w, bv1.x, bv1.y, bv1.z, bv1.w};
            #pragma unroll
            for (int i = 0; i < 8; i++)
                #pragma unroll
                for (int j = 0; j < 8; j++)
                    acc[i][j] += av[i] * bvv[j];
        }
    }

    int nbase = n0 + tx * 8;
    float bj[8];
    #pragma unroll
    for (int j = 0; j < 8; j++) bj[j] = bo[nbase + j];

    #pragma unroll
    for (int i = 0; i < 8; i++) {
        size_t mrow = (size_t)(m0 + ty * 8 + i) * DM;
        float4 r0 = make_float4(acc[i][0] + bj[0], acc[i][1] + bj[1],
                                acc[i][2] + bj[2], acc[i][3] + bj[3]);
        float4 r1 = make_float4(acc[i][4] + bj[4], acc[i][5] + bj[5],
                                acc[i][6] + bj[6], acc[i][7] + bj[7]);
        *(float4*)(out + mrow + nbase + 0) = r0;
        *(float4*)(out + mrow + nbase + 4) = r1;
    }
}

extern "C" void kernel_launch(void* const* d_in, const int* in_sizes, int n_in,
                              void* d_out, int out_size)
{
    const float* query = (const float*)d_in[0];
    const float* key_  = (const float*)d_in[1];
    const float* value = (const float*)d_in[2];
    const int*   mask  = (const int*)d_in[3];
    const float* Wq = (const float*)d_in[4];
    const float* bq = (const float*)d_in[5];
    const float* Wk = (const float*)d_in[6];
    const float* bk = (const float*)d_in[7];
    const float* Wv = (const float*)d_in[8];
    const float* bv = (const float*)d_in[9];
    const float* Wo = (const float*)d_in[10];
    const float* bo = (const float*)d_in[11];
    float* out = (float*)d_out;

    dim3 g1(DM / 128, (BB * S_LEN) / 128, 3);
    qkv_proj_kernel<<<g1, 256>>>(query, key_, value, Wq, bq, Wk, bk, Wv, bv);

    dim3 g2(S_LEN / 64, BB * NH);
    attn_kernel<<<g2, 128>>>(mask);

    dim3 g3(DM / 128, (BB * S_LEN) / 128);
    out_proj_kernel<<<g3, 256>>>(Wo, bo, out);
}